// round 16
// baseline (speedup 1.0000x reference)
#include <cuda_runtime.h>
#include <cuda_fp16.h>
#include <cstdint>

// ---------------------------------------------------------------------------
// PyG HypergraphConv:  out = (Dinv ⊙ H · Binv · Hᵀ · x) @ W + b
// CSR two-phase aggregation over fp16 rows (fp32 accumulation).
// Phase2 is FUSED into the GEMM: each CTA aggregates its 128 node rows into
// smem (fp16), then multiplies against W^T streamed via cp.async (3-stage).
// Critical path: zero_e -> hist_e -> offsets_e -> fill_e -> phase1 -> p2gemm.
// Stream B hides convx/convW and the node-side CSR build.
// ---------------------------------------------------------------------------

#define MAXN   50000
#define MAXNNZ 500000

__device__ __half g_x16 [MAXN * 256];
__device__ __half g_es16[MAXN * 256];
__device__ __half g_B16 [256 * 256];
__device__ int    g_node[MAXNNZ];
__device__ int    g_edge[MAXNNZ];
__device__ int    g_rank_e[MAXNNZ];
__device__ int    g_rank_n[MAXNNZ];
__device__ int    g_adj_e[MAXNNZ];
__device__ int    g_adj_n[MAXNNZ];
__device__ int    g_cnt_e[MAXN];
__device__ int    g_cnt_n[MAXN];
__device__ int    g_off_e[MAXN];
__device__ int    g_off_n[MAXN];
__device__ int    g_cursor[2];

__device__ __forceinline__ __half2 u2h2(uint32_t u) {
    __half2 h; *(uint32_t*)&h = u; return h;
}
__device__ __forceinline__ uint32_t h22u(__half2 h) {
    return *(uint32_t*)&h;
}
__device__ __forceinline__ int detect64(const unsigned int* raw) {
    __shared__ int sflag;
    if (threadIdx.x == 0) sflag = 1;
    __syncthreads();
    if (threadIdx.x < 128 && raw[2 * threadIdx.x + 1] != 0u) sflag = 0;
    __syncthreads();
    return sflag;
}

// ===================== stream B: convx + convW ===============================
__global__ void k_convB(const float4* __restrict__ x4, int n4,
                        const float* __restrict__ W, int b_convx) {
    int bx = blockIdx.x;
    if (bx < b_convx) {
        int i = bx * blockDim.x + threadIdx.x;
        if (i < n4) {
            float4 v = __ldg(x4 + i);
            uint2 o;
            o.x = h22u(__floats2half2_rn(v.x, v.y));
            o.y = h22u(__floats2half2_rn(v.z, v.w));
            ((uint2*)g_x16)[i] = o;
        }
    } else {
        int i = (bx - b_convx) * blockDim.x + threadIdx.x;
        if (i < 65536) {
            int n  = i & 255;
            int kk = i >> 8;
            g_B16[(size_t)n * 256 + kk] = __float2half_rn(__ldg(&W[kk * 256 + n]));
        }
    }
}

// ===================== graph prep ============================================
__global__ void k_zero_e(int E) {
    int i = blockIdx.x * blockDim.x + threadIdx.x;
    if (i < E) g_cnt_e[i] = 0;
    if (i == 0) g_cursor[0] = 0;
}

__global__ void k_zero_n(int N) {
    int i = blockIdx.x * blockDim.x + threadIdx.x;
    if (i < N) g_cnt_n[i] = 0;
    if (i == 0) g_cursor[1] = 0;
}

__global__ void k_hist_e(const unsigned int* __restrict__ raw, int nnz) {
    int is64 = detect64(raw);
    int i = blockIdx.x * blockDim.x + threadIdx.x;
    if (i >= nnz) return;
    int node, edge;
    if (is64) {
        const long long* p = (const long long*)raw;
        node = (int)p[i]; edge = (int)p[nnz + i];
    } else {
        const int* p = (const int*)raw;
        node = p[i]; edge = p[nnz + i];
    }
    g_node[i] = node; g_edge[i] = edge;
    g_rank_e[i] = atomicAdd(&g_cnt_e[edge], 1);
}

__global__ void k_hist_n(const unsigned int* __restrict__ raw, int nnz) {
    int is64 = detect64(raw);
    int i = blockIdx.x * blockDim.x + threadIdx.x;
    if (i >= nnz) return;
    int node;
    if (is64) node = (int)((const long long*)raw)[i];
    else      node = ((const int*)raw)[i];
    g_rank_n[i] = atomicAdd(&g_cnt_n[node], 1);
}

__global__ void k_offsets(int sel, int n) {
    __shared__ int warpsum[32];
    __shared__ int sbase;
    const int* cnt = sel ? g_cnt_n : g_cnt_e;
    int* off = sel ? g_off_n : g_off_e;
    int i = blockIdx.x * 1024 + threadIdx.x;
    int lane = threadIdx.x & 31;
    int wid  = threadIdx.x >> 5;
    int v = (i < n) ? cnt[i] : 0;

    int incl = v;
    #pragma unroll
    for (int d = 1; d < 32; d <<= 1) {
        int t = __shfl_up_sync(0xffffffffu, incl, d);
        if (lane >= d) incl += t;
    }
    if (lane == 31) warpsum[wid] = incl;
    __syncthreads();

    if (wid == 0) {
        int w = warpsum[lane];
        int wi = w;
        #pragma unroll
        for (int d = 1; d < 32; d <<= 1) {
            int t = __shfl_up_sync(0xffffffffu, wi, d);
            if (lane >= d) wi += t;
        }
        if (lane == 31) sbase = atomicAdd(&g_cursor[sel], wi);
        warpsum[lane] = wi - w;
    }
    __syncthreads();

    if (i < n) off[i] = sbase + warpsum[wid] + incl - v;
}

__global__ void k_fill_e(int nnz) {
    int i = blockIdx.x * blockDim.x + threadIdx.x;
    if (i >= nnz) return;
    g_adj_e[g_off_e[g_edge[i]] + g_rank_e[i]] = g_node[i];
}

__global__ void k_fill_n(int nnz) {
    int i = blockIdx.x * blockDim.x + threadIdx.x;
    if (i >= nnz) return;
    g_adj_n[g_off_n[g_node[i]] + g_rank_n[i]] = g_edge[i];
}

// ===================== phase 1: es16[e] = Binv * sum x16[i] ==================
__global__ void __launch_bounds__(256) k_phase1(int E) {
    int g    = (blockIdx.x * blockDim.x + threadIdx.x) >> 5;
    int lane = threadIdx.x & 31;
    if (g >= E) return;
    int s = g_off_e[g];
    int c = g_cnt_e[g];
    int t = s + c;
    float2 a[4];
    #pragma unroll
    for (int q = 0; q < 4; q++) a[q] = make_float2(0.f, 0.f);
    #pragma unroll 4
    for (int j = s; j < t; j++) {
        uint4 v = __ldg((const uint4*)g_x16 + (size_t)g_adj_e[j] * 32 + lane);
        float2 f0 = __half22float2(u2h2(v.x));
        float2 f1 = __half22float2(u2h2(v.y));
        float2 f2 = __half22float2(u2h2(v.z));
        float2 f3 = __half22float2(u2h2(v.w));
        a[0].x += f0.x; a[0].y += f0.y;
        a[1].x += f1.x; a[1].y += f1.y;
        a[2].x += f2.x; a[2].y += f2.y;
        a[3].x += f3.x; a[3].y += f3.y;
    }
    float binv = (c > 0) ? 1.0f / (float)c : 0.f;
    uint4 o;
    o.x = h22u(__floats2half2_rn(a[0].x * binv, a[0].y * binv));
    o.y = h22u(__floats2half2_rn(a[1].x * binv, a[1].y * binv));
    o.z = h22u(__floats2half2_rn(a[2].x * binv, a[2].y * binv));
    o.w = h22u(__floats2half2_rn(a[3].x * binv, a[3].y * binv));
    ((uint4*)g_es16)[(size_t)g * 32 + lane] = o;
}

// ===================== fused phase2 + GEMM ===================================
// One CTA per 128-node m-tile. Step 1: aggregate 128 rows (Dinv * sum es16)
// into smem A tile (fp16, stride 264 halves -> conflict-free ldmatrix).
// Step 2: C = A_smem @ B16^T + bias, two n-halves, B via cp.async 3 stages.
#define FSTR  264                           // A smem row stride in halves
#define BSTR  40                            // B stage row stride in halves
#define BSTG_H (128 * BSTR)
#define FSMEM (128 * FSTR * 2 + 3 * BSTG_H * 2)

__device__ __forceinline__ void ldsm_x4(uint32_t& r0, uint32_t& r1,
                                        uint32_t& r2, uint32_t& r3, uint32_t a) {
    asm volatile("ldmatrix.sync.aligned.m8n8.x4.shared.b16 {%0,%1,%2,%3}, [%4];"
                 : "=r"(r0), "=r"(r1), "=r"(r2), "=r"(r3) : "r"(a));
}
__device__ __forceinline__ void mma16816(float* c, const uint32_t* a, const uint32_t* b) {
    asm volatile("mma.sync.aligned.m16n8k16.row.col.f32.f16.f16.f32 "
                 "{%0,%1,%2,%3}, {%4,%5,%6,%7}, {%8,%9}, {%0,%1,%2,%3};"
                 : "+f"(c[0]), "+f"(c[1]), "+f"(c[2]), "+f"(c[3])
                 : "r"(a[0]), "r"(a[1]), "r"(a[2]), "r"(a[3]), "r"(b[0]), "r"(b[1]));
}
__device__ __forceinline__ uint32_t smem_u32(const void* p) {
    uint32_t a;
    asm("{ .reg .u64 t; cvta.to.shared.u64 t, %1; cvt.u32.u64 %0, t; }"
        : "=r"(a) : "l"(p));
    return a;
}
#define CP_ASYNC16(dst, src, sz) \
    asm volatile("cp.async.ca.shared.global [%0], [%1], 16, %2;" \
                 :: "r"(dst), "l"(src), "r"(sz) : "memory")
#define CP_COMMIT() asm volatile("cp.async.commit_group;" ::: "memory")
#define CP_WAIT(n)  asm volatile("cp.async.wait_group %0;" :: "n"(n) : "memory")

__global__ void __launch_bounds__(256) k_p2gemm(
    const float* __restrict__ hw, const float* __restrict__ bias,
    float* __restrict__ C, int M)
{
    extern __shared__ __align__(16) __half smem[];
    __half* sA = smem;                      // [128][FSTR]
    __half* sB = smem + 128 * FSTR;         // 3 stages of [128][BSTR]

    int tid  = threadIdx.x;
    int wid  = tid >> 5;
    int lane = tid & 31;
    int m0   = blockIdx.x * 128;
    int wm   = (wid >> 2) * 64;
    int wn   = (wid & 3) * 32;

    // ---- step 1: aggregate this tile's 128 node rows into sA ----
    #pragma unroll 1
    for (int r = 0; r < 16; r++) {
        int m = wid * 16 + r;
        int g = m0 + m;
        float2 a[4];
        #pragma unroll
        for (int q = 0; q < 4; q++) a[q] = make_float2(0.f, 0.f);
        float d = 0.f;
        if (g < M) {
            int s = g_off_n[g];
            int c = g_cnt_n[g];
            int t = s + c;
            #pragma unroll 4
            for (int j = s; j < t; j++) {
                int e = g_adj_n[j];
                d += __ldg(&hw[e]);
                uint4 v = __ldg((const uint4*)g_es16 + (size_t)e * 32 + lane);
                float2 f0 = __half22float2(u2h2(v.x));
                float2 f1 = __half22float2(u2h2(v.y));
                float2 f2 = __half22float2(u2h2(v.z));
                float2 f3 = __half22float2(u2h2(v.w));
                a[0].x += f0.x; a[0].y += f0.y;
                a[1].x += f1.x; a[1].y += f1.y;
                a[2].x += f2.x; a[2].y += f2.y;
                a[3].x += f3.x; a[3].y += f3.y;
            }
        }
        float dinv = (d > 0.f) ? 1.0f / d : 0.f;
        uint4 o;
        o.x = h22u(__floats2half2_rn(a[0].x * dinv, a[0].y * dinv));
        o.y = h22u(__floats2half2_rn(a[1].x * dinv, a[1].y * dinv));
        o.z = h22u(__floats2half2_rn(a[2].x * dinv, a[2].y * dinv));
        o.w = h22u(__floats2half2_rn(a[3].x * dinv, a[3].y * dinv));
        *(uint4*)(sA + (size_t)m * FSTR + lane * 8) = o;
    }
    __syncthreads();

    // ---- step 2: GEMM from smem A over two n-halves ----
    int lm = tid >> 1;                // B loader row 0..127
    int lq = (tid & 1) * 2;           // uint4 pair base

    int a_row  = wm + (lane & 15);
    int a_colx = (lane >> 4) << 3;
    int b_row  = wn + (lane & 7) + ((lane >> 4) << 3);
    int b_colx = ((lane >> 3) & 1) << 3;

    uint32_t sAu = smem_u32(sA);
    uint32_t sBu = smem_u32(sB);
    uint32_t bDstBase = smem_u32(sB + lm * BSTR + lq * 8);

    const uint4* Bg = (const uint4*)g_B16;

    #pragma unroll 1
    for (int nh = 0; nh < 2; nh++) {
        const uint4* bSrc = Bg + (size_t)(nh * 128 + lm) * 32 + lq;

        float acc[4][4][4];
        #pragma unroll
        for (int i = 0; i < 4; i++)
            #pragma unroll
            for (int j = 0; j < 4; j++)
                #pragma unroll
                for (int r = 0; r < 4; r++) acc[i][j][r] = 0.f;

        #define B_ISSUE(k, st) do {                                           \
            CP_ASYNC16(bDstBase + (st) * (BSTG_H * 2),      bSrc + (k) * 4,     16); \
            CP_ASYNC16(bDstBase + (st) * (BSTG_H * 2) + 16, bSrc + (k) * 4 + 1, 16); \
            CP_COMMIT();                                                      \
        } while (0)

        B_ISSUE(0, 0);
        B_ISSUE(1, 1);

        #pragma unroll
        for (int c = 0; c < 8; c++) {
            if (c < 7) CP_WAIT(1); else CP_WAIT(0);
            __syncthreads();

            int st = c % 3;
            uint32_t sBb = sBu + st * (BSTG_H * 2);
            #pragma unroll
            for (int ks = 0; ks < 32; ks += 16) {
                int kk = c * 32 + ks;
                uint32_t afr[4][4];
                #pragma unroll
                for (int f = 0; f < 4; f++) {
                    uint32_t addr = sAu + ((a_row + f * 16) * FSTR + kk + a_colx) * 2;
                    ldsm_x4(afr[f][0], afr[f][1], afr[f][2], afr[f][3], addr);
                }
                uint32_t bfr[4][2];
                #pragma unroll
                for (int h = 0; h < 2; h++) {
                    uint32_t addr = sBb + ((b_row + h * 16) * BSTR + ks + b_colx) * 2;
                    ldsm_x4(bfr[h * 2][0], bfr[h * 2][1],
                            bfr[h * 2 + 1][0], bfr[h * 2 + 1][1], addr);
                }
                #pragma unroll
                for (int mf = 0; mf < 4; mf++)
                    #pragma unroll
                    for (int nf = 0; nf < 4; nf++)
                        mma16816(acc[mf][nf], afr[mf], bfr[nf]);
            }

            if (c + 2 < 8) B_ISSUE(c + 2, (c + 2) % 3);
        }
        __syncthreads();   // protect sB stages before next nh reissues

        // epilogue for this n-half
        int n0 = nh * 128;
        float bv[8];
        #pragma unroll
        for (int nf = 0; nf < 4; nf++) {
            int gc = n0 + wn + nf * 8 + (lane & 3) * 2;
            bv[nf * 2]     = __ldg(&bias[gc]);
            bv[nf * 2 + 1] = __ldg(&bias[gc + 1]);
        }
        #pragma unroll
        for (int mf = 0; mf < 4; mf++) {
            int gr0 = m0 + wm + mf * 16 + (lane >> 2);
            #pragma unroll
            for (int nf = 0; nf < 4; nf++) {
                int gc = n0 + wn + nf * 8 + (lane & 3) * 2;
                if (gr0 < M) {
                    float2 o0 = make_float2(acc[mf][nf][0] + bv[nf * 2],
                                            acc[mf][nf][1] + bv[nf * 2 + 1]);
                    *(float2*)(C + (size_t)gr0 * 256 + gc) = o0;
                }
                if (gr0 + 8 < M) {
                    float2 o1 = make_float2(acc[mf][nf][2] + bv[nf * 2],
                                            acc[mf][nf][3] + bv[nf * 2 + 1]);
                    *(float2*)(C + (size_t)(gr0 + 8) * 256 + gc) = o1;
                }
            }
        }
    }
}

// ---------------------------------------------------------------------------
extern "C" void kernel_launch(void* const* d_in, const int* in_sizes, int n_in,
                              void* d_out, int out_size) {
    const float* x    = (const float*)d_in[0];
    const void*  hidx = d_in[1];
    const float* hw   = (const float*)d_in[2];
    const float* W    = (const float*)d_in[3];
    const float* bias = (const float*)d_in[4];
    float*       out  = (float*)d_out;

    int N   = in_sizes[0] / 256;
    int NNZ = in_sizes[1] / 2;
    int E   = in_sizes[2];

    static cudaStream_t s2 = nullptr;
    static cudaEvent_t evFork, evX, evHistE, evNode;
    if (!s2) {
        cudaStreamCreateWithFlags(&s2, cudaStreamNonBlocking);
        cudaEventCreateWithFlags(&evFork,  cudaEventDisableTiming);
        cudaEventCreateWithFlags(&evX,     cudaEventDisableTiming);
        cudaEventCreateWithFlags(&evHistE, cudaEventDisableTiming);
        cudaEventCreateWithFlags(&evNode,  cudaEventDisableTiming);
        cudaFuncSetAttribute(k_p2gemm,
                             cudaFuncAttributeMaxDynamicSharedMemorySize, FSMEM);
    }

    // stream B: fp16 conversions
    cudaEventRecord(evFork, 0);
    cudaStreamWaitEvent(s2, evFork, 0);
    int n4 = N * 64;
    int b_convx = (n4 + 255) / 256;
    k_convB<<<b_convx + 256, 256, 0, s2>>>((const float4*)x, n4, W, b_convx);
    cudaEventRecord(evX, s2);

    // stream A: edge-side critical path
    k_zero_e<<<(E + 255) / 256, 256>>>(E);
    k_hist_e<<<(NNZ + 255) / 256, 256>>>((const unsigned int*)hidx, NNZ);
    cudaEventRecord(evHistE, 0);
    k_offsets<<<(E + 1023) / 1024, 1024>>>(0, E);
    k_fill_e<<<(NNZ + 255) / 256, 256>>>(NNZ);

    // phase1 needs x16 (B) + edge CSR (A)
    cudaStreamWaitEvent(0, evX, 0);
    k_phase1<<<(E * 32 + 255) / 256, 256>>>(E);

    // stream B: node-side CSR build (concurrent with fill_e/phase1)
    cudaStreamWaitEvent(s2, evFork, 0);
    k_zero_n<<<(N + 255) / 256, 256, 0, s2>>>(N);
    k_hist_n<<<(NNZ + 255) / 256, 256, 0, s2>>>((const unsigned int*)hidx, NNZ);
    k_offsets<<<(N + 1023) / 1024, 1024, 0, s2>>>(1, N);
    cudaStreamWaitEvent(s2, evHistE, 0);
    k_fill_n<<<(NNZ + 255) / 256, 256, 0, s2>>>(NNZ);
    cudaEventRecord(evNode, s2);

    // fused phase2+GEMM on stream A
    cudaStreamWaitEvent(0, evNode, 0);
    int mtiles = (N + 127) / 128;
    k_p2gemm<<<mtiles, 256, FSMEM>>>(hw, bias, out, N);
}

// round 17
// speedup vs baseline: 1.2434x; 1.2434x over previous
#include <cuda_runtime.h>
#include <cuda_fp16.h>
#include <cstdint>

// ---------------------------------------------------------------------------
// PyG HypergraphConv:  out = (Dinv ⊙ H · Binv · Hᵀ · x) @ W + b
// CSR two-phase aggregation over fp16 rows (fp32 accumulation).
// Critical path: zero_e -> hist_e -> offsets_e -> fill_e -> phase1 -> phase2
// -> gemm. Stream B hides convx/convW and the whole node-side CSR build.
// cp.async 3-stage pipelined fp16 mma.sync GEMM (K=256).
// (R15 configuration — measured best at 122.9 us; R16 fusion regressed.)
// ---------------------------------------------------------------------------

#define MAXN   50000
#define MAXNNZ 500000

__device__ __half g_x16 [MAXN * 256];
__device__ __half g_es16[MAXN * 256];
__device__ __half g_A16 [MAXN * 256];
__device__ __half g_B16 [256 * 256];
__device__ int    g_node[MAXNNZ];
__device__ int    g_edge[MAXNNZ];
__device__ int    g_rank_e[MAXNNZ];
__device__ int    g_rank_n[MAXNNZ];
__device__ int    g_adj_e[MAXNNZ];
__device__ int    g_adj_n[MAXNNZ];
__device__ int    g_cnt_e[MAXN];
__device__ int    g_cnt_n[MAXN];
__device__ int    g_off_e[MAXN];
__device__ int    g_off_n[MAXN];
__device__ int    g_cursor[2];

__device__ __forceinline__ __half2 u2h2(uint32_t u) {
    __half2 h; *(uint32_t*)&h = u; return h;
}
__device__ __forceinline__ uint32_t h22u(__half2 h) {
    return *(uint32_t*)&h;
}
__device__ __forceinline__ int detect64(const unsigned int* raw) {
    __shared__ int sflag;
    if (threadIdx.x == 0) sflag = 1;
    __syncthreads();
    if (threadIdx.x < 128 && raw[2 * threadIdx.x + 1] != 0u) sflag = 0;
    __syncthreads();
    return sflag;
}

// ===================== stream B: convx + convW ===============================
__global__ void k_convB(const float4* __restrict__ x4, int n4,
                        const float* __restrict__ W, int b_convx) {
    int bx = blockIdx.x;
    if (bx < b_convx) {
        int i = bx * blockDim.x + threadIdx.x;
        if (i < n4) {
            float4 v = __ldg(x4 + i);
            uint2 o;
            o.x = h22u(__floats2half2_rn(v.x, v.y));
            o.y = h22u(__floats2half2_rn(v.z, v.w));
            ((uint2*)g_x16)[i] = o;
        }
    } else {
        int i = (bx - b_convx) * blockDim.x + threadIdx.x;
        if (i < 65536) {
            int n  = i & 255;
            int kk = i >> 8;
            g_B16[(size_t)n * 256 + kk] = __float2half_rn(__ldg(&W[kk * 256 + n]));
        }
    }
}

// ===================== graph prep ============================================
__global__ void k_zero_e(int E) {
    int i = blockIdx.x * blockDim.x + threadIdx.x;
    if (i < E) g_cnt_e[i] = 0;
    if (i == 0) g_cursor[0] = 0;
}

__global__ void k_zero_n(int N) {
    int i = blockIdx.x * blockDim.x + threadIdx.x;
    if (i < N) g_cnt_n[i] = 0;
    if (i == 0) g_cursor[1] = 0;
}

__global__ void k_hist_e(const unsigned int* __restrict__ raw, int nnz) {
    int is64 = detect64(raw);
    int i = blockIdx.x * blockDim.x + threadIdx.x;
    if (i >= nnz) return;
    int node, edge;
    if (is64) {
        const long long* p = (const long long*)raw;
        node = (int)p[i]; edge = (int)p[nnz + i];
    } else {
        const int* p = (const int*)raw;
        node = p[i]; edge = p[nnz + i];
    }
    g_node[i] = node; g_edge[i] = edge;
    g_rank_e[i] = atomicAdd(&g_cnt_e[edge], 1);
}

__global__ void k_hist_n(const unsigned int* __restrict__ raw, int nnz) {
    int is64 = detect64(raw);
    int i = blockIdx.x * blockDim.x + threadIdx.x;
    if (i >= nnz) return;
    int node;
    if (is64) node = (int)((const long long*)raw)[i];
    else      node = ((const int*)raw)[i];
    g_rank_n[i] = atomicAdd(&g_cnt_n[node], 1);
}

// warp-shuffle single-pass offsets for ONE array (sel: 0=edge, 1=node)
__global__ void k_offsets(int sel, int n) {
    __shared__ int warpsum[32];
    __shared__ int sbase;
    const int* cnt = sel ? g_cnt_n : g_cnt_e;
    int* off = sel ? g_off_n : g_off_e;
    int i = blockIdx.x * 1024 + threadIdx.x;
    int lane = threadIdx.x & 31;
    int wid  = threadIdx.x >> 5;
    int v = (i < n) ? cnt[i] : 0;

    int incl = v;
    #pragma unroll
    for (int d = 1; d < 32; d <<= 1) {
        int t = __shfl_up_sync(0xffffffffu, incl, d);
        if (lane >= d) incl += t;
    }
    if (lane == 31) warpsum[wid] = incl;
    __syncthreads();

    if (wid == 0) {
        int w = warpsum[lane];
        int wi = w;
        #pragma unroll
        for (int d = 1; d < 32; d <<= 1) {
            int t = __shfl_up_sync(0xffffffffu, wi, d);
            if (lane >= d) wi += t;
        }
        if (lane == 31) sbase = atomicAdd(&g_cursor[sel], wi);
        warpsum[lane] = wi - w;
    }
    __syncthreads();

    if (i < n) off[i] = sbase + warpsum[wid] + incl - v;
}

__global__ void k_fill_e(int nnz) {
    int i = blockIdx.x * blockDim.x + threadIdx.x;
    if (i >= nnz) return;
    g_adj_e[g_off_e[g_edge[i]] + g_rank_e[i]] = g_node[i];
}

__global__ void k_fill_n(int nnz) {
    int i = blockIdx.x * blockDim.x + threadIdx.x;
    if (i >= nnz) return;
    g_adj_n[g_off_n[g_node[i]] + g_rank_n[i]] = g_edge[i];
}

// ===================== phase 1: es16[e] = Binv * sum x16[i] ==================
__global__ void __launch_bounds__(256) k_phase1(int E) {
    int g    = (blockIdx.x * blockDim.x + threadIdx.x) >> 5;
    int lane = threadIdx.x & 31;
    if (g >= E) return;
    int s = g_off_e[g];
    int c = g_cnt_e[g];
    int t = s + c;
    float2 a[4];
    #pragma unroll
    for (int q = 0; q < 4; q++) a[q] = make_float2(0.f, 0.f);
    #pragma unroll 4
    for (int j = s; j < t; j++) {
        uint4 v = __ldg((const uint4*)g_x16 + (size_t)g_adj_e[j] * 32 + lane);
        float2 f0 = __half22float2(u2h2(v.x));
        float2 f1 = __half22float2(u2h2(v.y));
        float2 f2 = __half22float2(u2h2(v.z));
        float2 f3 = __half22float2(u2h2(v.w));
        a[0].x += f0.x; a[0].y += f0.y;
        a[1].x += f1.x; a[1].y += f1.y;
        a[2].x += f2.x; a[2].y += f2.y;
        a[3].x += f3.x; a[3].y += f3.y;
    }
    float binv = (c > 0) ? 1.0f / (float)c : 0.f;
    uint4 o;
    o.x = h22u(__floats2half2_rn(a[0].x * binv, a[0].y * binv));
    o.y = h22u(__floats2half2_rn(a[1].x * binv, a[1].y * binv));
    o.z = h22u(__floats2half2_rn(a[2].x * binv, a[2].y * binv));
    o.w = h22u(__floats2half2_rn(a[3].x * binv, a[3].y * binv));
    ((uint4*)g_es16)[(size_t)g * 32 + lane] = o;
}

// ===================== phase 2: A16[i] = fp16(Dinv * sum es16[e]) ============
__global__ void __launch_bounds__(256) k_phase2(const float* __restrict__ hw, int N) {
    int g    = (blockIdx.x * blockDim.x + threadIdx.x) >> 5;
    int lane = threadIdx.x & 31;
    if (g >= N) return;
    int s = g_off_n[g];
    int c = g_cnt_n[g];
    int t = s + c;
    float2 a[4];
    #pragma unroll
    for (int q = 0; q < 4; q++) a[q] = make_float2(0.f, 0.f);
    float d = 0.f;
    #pragma unroll 4
    for (int j = s; j < t; j++) {
        int e = g_adj_n[j];
        d += __ldg(&hw[e]);
        uint4 v = __ldg((const uint4*)g_es16 + (size_t)e * 32 + lane);
        float2 f0 = __half22float2(u2h2(v.x));
        float2 f1 = __half22float2(u2h2(v.y));
        float2 f2 = __half22float2(u2h2(v.z));
        float2 f3 = __half22float2(u2h2(v.w));
        a[0].x += f0.x; a[0].y += f0.y;
        a[1].x += f1.x; a[1].y += f1.y;
        a[2].x += f2.x; a[2].y += f2.y;
        a[3].x += f3.x; a[3].y += f3.y;
    }
    float dinv = (d > 0.f) ? 1.0f / d : 0.f;
    uint4 o;
    o.x = h22u(__floats2half2_rn(a[0].x * dinv, a[0].y * dinv));
    o.y = h22u(__floats2half2_rn(a[1].x * dinv, a[1].y * dinv));
    o.z = h22u(__floats2half2_rn(a[2].x * dinv, a[2].y * dinv));
    o.w = h22u(__floats2half2_rn(a[3].x * dinv, a[3].y * dinv));
    ((uint4*)g_A16)[(size_t)g * 32 + lane] = o;
}

// ===================== mma.sync GEMM with cp.async 3-stage pipeline ==========
#define ASTR 40
#define STG_H (128 * ASTR)
#define GSMEM (2 * 3 * STG_H * 2)

__device__ __forceinline__ void ldsm_x4(uint32_t& r0, uint32_t& r1,
                                        uint32_t& r2, uint32_t& r3, uint32_t a) {
    asm volatile("ldmatrix.sync.aligned.m8n8.x4.shared.b16 {%0,%1,%2,%3}, [%4];"
                 : "=r"(r0), "=r"(r1), "=r"(r2), "=r"(r3) : "r"(a));
}
__device__ __forceinline__ void mma16816(float* c, const uint32_t* a, const uint32_t* b) {
    asm volatile("mma.sync.aligned.m16n8k16.row.col.f32.f16.f16.f32 "
                 "{%0,%1,%2,%3}, {%4,%5,%6,%7}, {%8,%9}, {%0,%1,%2,%3};"
                 : "+f"(c[0]), "+f"(c[1]), "+f"(c[2]), "+f"(c[3])
                 : "r"(a[0]), "r"(a[1]), "r"(a[2]), "r"(a[3]), "r"(b[0]), "r"(b[1]));
}
__device__ __forceinline__ uint32_t smem_u32(const void* p) {
    uint32_t a;
    asm("{ .reg .u64 t; cvta.to.shared.u64 t, %1; cvt.u32.u64 %0, t; }"
        : "=r"(a) : "l"(p));
    return a;
}
#define CP_ASYNC16(dst, src, sz) \
    asm volatile("cp.async.ca.shared.global [%0], [%1], 16, %2;" \
                 :: "r"(dst), "l"(src), "r"(sz) : "memory")
#define CP_COMMIT() asm volatile("cp.async.commit_group;" ::: "memory")
#define CP_WAIT(n)  asm volatile("cp.async.wait_group %0;" :: "n"(n) : "memory")

__global__ void __launch_bounds__(256) k_gemm_mma(
    const float* __restrict__ bias, float* __restrict__ C, int M)
{
    extern __shared__ __align__(16) __half smem[];
    __half* sA = smem;
    __half* sB = smem + 3 * STG_H;

    int tid  = threadIdx.x;
    int wid  = tid >> 5;
    int lane = tid & 31;
    int m0   = blockIdx.y * 128;
    int n0   = blockIdx.x * 128;
    int wm   = (wid >> 2) * 64;
    int wn   = (wid & 3) * 32;

    float acc[4][4][4];
    #pragma unroll
    for (int i = 0; i < 4; i++)
        #pragma unroll
        for (int j = 0; j < 4; j++)
            #pragma unroll
            for (int r = 0; r < 4; r++) acc[i][j][r] = 0.f;

    int lm = tid >> 1;
    int lq = (tid & 1) * 2;

    int a_row = wm + (lane & 15);
    int a_colx = (lane >> 4) << 3;
    int b_row = wn + (lane & 7) + ((lane >> 4) << 3);
    int b_colx = ((lane >> 3) & 1) << 3;

    const uint4* Ag = (const uint4*)g_A16;
    const uint4* Bg = (const uint4*)g_B16;

    int gm = m0 + lm;
    int gmc = (gm < M) ? gm : (M - 1);
    int asz = (gm < M) ? 16 : 0;
    const uint4* aSrc = Ag + (size_t)gmc * 32 + lq;
    const uint4* bSrc = Bg + (size_t)(n0 + lm) * 32 + lq;
    uint32_t aDstBase = smem_u32(sA + lm * ASTR + lq * 8);
    uint32_t bDstBase = smem_u32(sB + lm * ASTR + lq * 8);

    #define GEMM_ISSUE(k, st) do {                                            \
        CP_ASYNC16(aDstBase + (st) * (STG_H * 2),      aSrc + (k) * 4,     asz); \
        CP_ASYNC16(aDstBase + (st) * (STG_H * 2) + 16, aSrc + (k) * 4 + 1, asz); \
        CP_ASYNC16(bDstBase + (st) * (STG_H * 2),      bSrc + (k) * 4,     16);  \
        CP_ASYNC16(bDstBase + (st) * (STG_H * 2) + 16, bSrc + (k) * 4 + 1, 16);  \
        CP_COMMIT();                                                          \
    } while (0)

    GEMM_ISSUE(0, 0);
    GEMM_ISSUE(1, 1);

    uint32_t sAu = smem_u32(sA);
    uint32_t sBu = smem_u32(sB);

    #pragma unroll
    for (int c = 0; c < 8; c++) {
        if (c < 7) CP_WAIT(1); else CP_WAIT(0);
        __syncthreads();

        int st = c % 3;
        uint32_t sAb = sAu + st * (STG_H * 2);
        uint32_t sBb = sBu + st * (STG_H * 2);
        #pragma unroll
        for (int ks = 0; ks < 32; ks += 16) {
            uint32_t afr[4][4];
            #pragma unroll
            for (int f = 0; f < 4; f++) {
                uint32_t addr = sAb + ((a_row + f * 16) * ASTR + ks + a_colx) * 2;
                ldsm_x4(afr[f][0], afr[f][1], afr[f][2], afr[f][3], addr);
            }
            uint32_t bfr[4][2];
            #pragma unroll
            for (int h = 0; h < 2; h++) {
                uint32_t addr = sBb + ((b_row + h * 16) * ASTR + ks + b_colx) * 2;
                ldsm_x4(bfr[h * 2][0], bfr[h * 2][1],
                        bfr[h * 2 + 1][0], bfr[h * 2 + 1][1], addr);
            }
            #pragma unroll
            for (int mf = 0; mf < 4; mf++)
                #pragma unroll
                for (int nf = 0; nf < 4; nf++)
                    mma16816(acc[mf][nf], afr[mf], bfr[nf]);
        }

        if (c + 2 < 8) GEMM_ISSUE(c + 2, (c + 2) % 3);
    }

    float bv[8];
    #pragma unroll
    for (int nf = 0; nf < 4; nf++) {
        int gc = n0 + wn + nf * 8 + (lane & 3) * 2;
        bv[nf * 2]     = __ldg(&bias[gc]);
        bv[nf * 2 + 1] = __ldg(&bias[gc + 1]);
    }
    #pragma unroll
    for (int mf = 0; mf < 4; mf++) {
        int gr0 = m0 + wm + mf * 16 + (lane >> 2);
        #pragma unroll
        for (int nf = 0; nf < 4; nf++) {
            int gc = n0 + wn + nf * 8 + (lane & 3) * 2;
            if (gr0 < M) {
                float2 o0 = make_float2(acc[mf][nf][0] + bv[nf * 2],
                                        acc[mf][nf][1] + bv[nf * 2 + 1]);
                *(float2*)(C + (size_t)gr0 * 256 + gc) = o0;
            }
            if (gr0 + 8 < M) {
                float2 o1 = make_float2(acc[mf][nf][2] + bv[nf * 2],
                                        acc[mf][nf][3] + bv[nf * 2 + 1]);
                *(float2*)(C + (size_t)(gr0 + 8) * 256 + gc) = o1;
            }
        }
    }
}

// ---------------------------------------------------------------------------
extern "C" void kernel_launch(void* const* d_in, const int* in_sizes, int n_in,
                              void* d_out, int out_size) {
    const float* x    = (const float*)d_in[0];
    const void*  hidx = d_in[1];
    const float* hw   = (const float*)d_in[2];
    const float* W    = (const float*)d_in[3];
    const float* bias = (const float*)d_in[4];
    float*       out  = (float*)d_out;

    int N   = in_sizes[0] / 256;
    int NNZ = in_sizes[1] / 2;
    int E   = in_sizes[2];

    static cudaStream_t s2 = nullptr;
    static cudaEvent_t evFork, evX, evHistE, evNode;
    if (!s2) {
        cudaStreamCreateWithFlags(&s2, cudaStreamNonBlocking);
        cudaEventCreateWithFlags(&evFork,  cudaEventDisableTiming);
        cudaEventCreateWithFlags(&evX,     cudaEventDisableTiming);
        cudaEventCreateWithFlags(&evHistE, cudaEventDisableTiming);
        cudaEventCreateWithFlags(&evNode,  cudaEventDisableTiming);
        cudaFuncSetAttribute(k_gemm_mma,
                             cudaFuncAttributeMaxDynamicSharedMemorySize, GSMEM);
    }

    // --- stream B: fp16 conversions ---
    cudaEventRecord(evFork, 0);
    cudaStreamWaitEvent(s2, evFork, 0);
    int n4 = N * 64;
    int b_convx = (n4 + 255) / 256;
    k_convB<<<b_convx + 256, 256, 0, s2>>>((const float4*)x, n4, W, b_convx);
    cudaEventRecord(evX, s2);

    // --- stream A: edge-side critical path ---
    k_zero_e<<<(E + 255) / 256, 256>>>(E);
    k_hist_e<<<(NNZ + 255) / 256, 256>>>((const unsigned int*)hidx, NNZ);
    cudaEventRecord(evHistE, 0);
    k_offsets<<<(E + 1023) / 1024, 1024>>>(0, E);
    k_fill_e<<<(NNZ + 255) / 256, 256>>>(NNZ);

    // --- phase1 (6th launch; profiled by ncu -s 5 -c 1) ---
    cudaStreamWaitEvent(0, evX, 0);
    k_phase1<<<(E * 32 + 255) / 256, 256>>>(E);

    // --- stream B: node-side CSR build (concurrent with fill_e/phase1) ---
    cudaStreamWaitEvent(s2, evFork, 0);
    k_zero_n<<<(N + 255) / 256, 256, 0, s2>>>(N);
    k_hist_n<<<(NNZ + 255) / 256, 256, 0, s2>>>((const unsigned int*)hidx, NNZ);
    k_offsets<<<(N + 1023) / 1024, 1024, 0, s2>>>(1, N);
    cudaStreamWaitEvent(s2, evHistE, 0);
    k_fill_n<<<(NNZ + 255) / 256, 256, 0, s2>>>(NNZ);
    cudaEventRecord(evNode, s2);

    // --- phase2 + gemm on stream A ---
    cudaStreamWaitEvent(0, evNode, 0);
    k_phase2<<<(N * 32 + 255) / 256, 256>>>(hw, N);

    dim3 g(2, (N + 127) / 128);
    k_gemm_mma<<<g, 256, GSMEM>>>(bias, out, N);
}